// round 14
// baseline (speedup 1.0000x reference)
#include <cuda_runtime.h>
#include <cuda_bf16.h>
#include <cstdint>

#define DDIM    256
#define KCODES  1024
#define MTOT    32768
#define BM      128      // tokens per CTA
#define NC      128      // codes per n-chunk
#define KC      32       // dims per k-chunk
#define SROWB   40       // smem row stride in bf16 (80B): conflict-free, 16B-aligned
#define EPSF    5.0f     // >> worst-case bf16-rounding distance error (~1.3)

__device__ float g_c_sq[KCODES];
__device__ float g_dist[(size_t)MTOT * KCODES];          // 128MB scratch
__device__ __nv_bfloat16 g_zb[(size_t)MTOT * DDIM];      // 16MB bf16 z
__device__ __nv_bfloat16 g_cbb[(size_t)KCODES * DDIM];   // 0.5MB bf16 codebook

__device__ __forceinline__ void mma_bf16(float* c, const uint32_t* a, const uint32_t* b) {
    asm volatile(
        "mma.sync.aligned.m16n8k16.row.col.f32.bf16.bf16.f32 "
        "{%0,%1,%2,%3}, {%4,%5,%6,%7}, {%8,%9}, {%0,%1,%2,%3};"
        : "+f"(c[0]), "+f"(c[1]), "+f"(c[2]), "+f"(c[3])
        : "r"(a[0]), "r"(a[1]), "r"(a[2]), "r"(a[3]), "r"(b[0]), "r"(b[1]));
}

// ---------------- prologue kernels ----------------
__global__ void csq_kernel(const float* __restrict__ cb) {
    int warp = (blockIdx.x * blockDim.x + threadIdx.x) >> 5;
    int lane = threadIdx.x & 31;
    if (warp >= KCODES) return;
    const float* row = cb + (size_t)warp * DDIM;
    float s = 0.f;
    #pragma unroll
    for (int d = lane; d < DDIM; d += 32) { float v = row[d]; s += v * v; }
    #pragma unroll
    for (int o = 16; o; o >>= 1) s += __shfl_xor_sync(0xffffffffu, s, o);
    if (lane == 0) g_c_sq[warp] = s;
}

__global__ void z_tobf16_kernel(const float* __restrict__ src) {
    int i = blockIdx.x * blockDim.x + threadIdx.x;
    if (i >= MTOT * DDIM / 4) return;
    float4 v = ((const float4*)src)[i];
    ((__nv_bfloat162*)g_zb)[2 * i]     = __floats2bfloat162_rn(v.x, v.y);
    ((__nv_bfloat162*)g_zb)[2 * i + 1] = __floats2bfloat162_rn(v.z, v.w);
}
__global__ void cb_tobf16_kernel(const float* __restrict__ src) {
    int i = blockIdx.x * blockDim.x + threadIdx.x;
    if (i >= KCODES * DDIM / 4) return;
    float4 v = ((const float4*)src)[i];
    ((__nv_bfloat162*)g_cbb)[2 * i]     = __floats2bfloat162_rn(v.x, v.y);
    ((__nv_bfloat162*)g_cbb)[2 * i + 1] = __floats2bfloat162_rn(v.z, v.w);
}

// ---------------- Phase 1: bf16 mma.sync, register-prefetch double buffer ----
// 8 warps in 4x2 grid; warp tile m32 x n64; 64 linear (n0,k0) iterations.
// Staging: z tile 128x32 bf16 (512 x 16B chunks) + cb tile same. 2 chunks each
// per thread per tile -> 4 uint4 prefetch registers.
__global__ __launch_bounds__(256, 2)
void vq_phase1(void) {
    __shared__ __align__(16) char zsmem[BM * SROWB * 2];   // 10240 B
    __shared__ __align__(16) char csmem[NC * SROWB * 2];   // 10240 B
    __shared__ float s_csq[KCODES];                         // 4 KB

    const int tid = threadIdx.x;
    const int w   = tid >> 5;
    const int l   = tid & 31;
    const int wm  = w & 3;
    const int wn  = w >> 2;
    const int m0  = blockIdx.x * BM;
    const int lg  = l >> 2;
    const int lt  = l & 3;
    const int srow = tid >> 2;          // staging row for this thread's chunks
    const int sq   = tid & 3;           // 16B-chunk column

    #pragma unroll
    for (int i = 0; i < KCODES / 256; i++) s_csq[tid + i * 256] = g_c_sq[tid + i * 256];

    float acc[2][8][4];
    uint4 pz[2], pc[2];

    // prefetch iteration 0 (n0=0, k0=0)
    {
        const __nv_bfloat16* zsrc = g_zb + (size_t)(m0 + srow) * DDIM + 8 * sq;
        pz[0] = *(const uint4*)zsrc;
        pz[1] = *(const uint4*)(zsrc + 64 * DDIM);
        const __nv_bfloat16* csrc = g_cbb + (size_t)srow * DDIM + 8 * sq;
        pc[0] = *(const uint4*)csrc;
        pc[1] = *(const uint4*)(csrc + 64 * DDIM);
    }

    for (int idx = 0; idx < 64; idx++) {
        __syncthreads();              // previous compute done: smem reusable
        // store prefetched tile
        *(uint4*)(zsmem + srow * (SROWB * 2) + 16 * sq)        = pz[0];
        *(uint4*)(zsmem + (srow + 64) * (SROWB * 2) + 16 * sq) = pz[1];
        *(uint4*)(csmem + srow * (SROWB * 2) + 16 * sq)        = pc[0];
        *(uint4*)(csmem + (srow + 64) * (SROWB * 2) + 16 * sq) = pc[1];
        __syncthreads();              // tile visible

        // issue next tile's LDGs (latency hidden behind MMA block)
        if (idx + 1 < 64) {
            const int nn0 = ((idx + 1) >> 3) * NC;
            const int nk0 = ((idx + 1) & 7) * KC;
            const __nv_bfloat16* zsrc = g_zb + (size_t)(m0 + srow) * DDIM + nk0 + 8 * sq;
            pz[0] = *(const uint4*)zsrc;
            pz[1] = *(const uint4*)(zsrc + 64 * DDIM);
            const __nv_bfloat16* csrc = g_cbb + (size_t)(nn0 + srow) * DDIM + nk0 + 8 * sq;
            pc[0] = *(const uint4*)csrc;
            pc[1] = *(const uint4*)(csrc + 64 * DDIM);
        }

        if ((idx & 7) == 0) {
            #pragma unroll
            for (int it = 0; it < 2; it++)
                #pragma unroll
                for (int j = 0; j < 8; j++)
                    #pragma unroll
                    for (int q = 0; q < 4; q++) acc[it][j][q] = 0.f;
        }

        #pragma unroll
        for (int ks = 0; ks < KC / 16; ks++) {     // 2 k16 steps
            const int kb = ks * 32;                // byte offset of k16 block
            uint32_t afr[2][4];
            #pragma unroll
            for (int it = 0; it < 2; it++) {
                const char* ab = zsmem + (wm * 32 + it * 16) * (SROWB * 2) + kb + 4 * lt;
                afr[it][0] = *(const uint32_t*)(ab + (lg    ) * (SROWB * 2));
                afr[it][1] = *(const uint32_t*)(ab + (lg + 8) * (SROWB * 2));
                afr[it][2] = *(const uint32_t*)(ab + (lg    ) * (SROWB * 2) + 16);
                afr[it][3] = *(const uint32_t*)(ab + (lg + 8) * (SROWB * 2) + 16);
            }
            uint32_t bfr[8][2];
            #pragma unroll
            for (int j = 0; j < 8; j++) {
                const char* bb = csmem + (wn * 64 + j * 8 + lg) * (SROWB * 2) + kb + 4 * lt;
                bfr[j][0] = *(const uint32_t*)(bb);
                bfr[j][1] = *(const uint32_t*)(bb + 16);
            }
            #pragma unroll
            for (int it = 0; it < 2; it++)
                #pragma unroll
                for (int j = 0; j < 8; j++)
                    mma_bf16(acc[it][j], afr[it], bfr[j]);
        }

        if ((idx & 7) == 7) {                 // n-chunk done: emit distances
            const int n0 = (idx >> 3) * NC;
            #pragma unroll
            for (int it = 0; it < 2; it++) {
                const int r0 = wm * 32 + it * 16 + lg;
                #pragma unroll
                for (int j = 0; j < 8; j++) {
                    const int c0 = n0 + wn * 64 + j * 8 + 2 * lt;
                    float cq0 = s_csq[c0], cq1 = s_csq[c0 + 1];
                    float2 lo, hi;
                    lo.x = fmaf(-2.f, acc[it][j][0], cq0);
                    lo.y = fmaf(-2.f, acc[it][j][1], cq1);
                    hi.x = fmaf(-2.f, acc[it][j][2], cq0);
                    hi.y = fmaf(-2.f, acc[it][j][3], cq1);
                    *(float2*)(g_dist + (size_t)(m0 + r0    ) * KCODES + c0) = lo;
                    *(float2*)(g_dist + (size_t)(m0 + r0 + 8) * KCODES + c0) = hi;
                }
            }
        }
    }
}

// ---------------- Phase 2: exact argmin among EPS-candidates + gather ----------------
__global__ __launch_bounds__(256)
void vq_phase2(const float* __restrict__ z, const float* __restrict__ cb,
               float* __restrict__ zq, float* __restrict__ idx_out) {
    const int m    = (blockIdx.x * blockDim.x + threadIdx.x) >> 5;   // one warp/token
    const int lane = threadIdx.x & 31;

    const float4* d4 = (const float4*)(g_dist + (size_t)m * KCODES);
    float4 vals[8];
    #pragma unroll
    for (int i = 0; i < 8; i++) vals[i] = d4[i * 32 + lane];

    // approx min (lowest index on ties)
    float amin = 3.402823466e38f; int aidx = KCODES;
    #pragma unroll
    for (int i = 0; i < 8; i++) {
        int base = (i * 32 + lane) * 4;
        float v[4] = {vals[i].x, vals[i].y, vals[i].z, vals[i].w};
        #pragma unroll
        for (int j = 0; j < 4; j++)
            if (v[j] < amin) { amin = v[j]; aidx = base + j; }
    }
    #pragma unroll
    for (int o = 16; o; o >>= 1) {
        float ob = __shfl_xor_sync(0xffffffffu, amin, o);
        int   oi = __shfl_xor_sync(0xffffffffu, aidx, o);
        if (ob < amin || (ob == amin && oi < aidx)) { amin = ob; aidx = oi; }
    }
    const float thresh = amin + EPSF;

    // exact fp32 rescore of candidates within EPS of approx min
    float ebest = 3.402823466e38f; int eidx = KCODES;
    const float* zr = z + (size_t)m * DDIM;
    #pragma unroll
    for (int i = 0; i < 8; i++) {
        int base = (i * 32 + lane) * 4;
        float v[4] = {vals[i].x, vals[i].y, vals[i].z, vals[i].w};
        #pragma unroll
        for (int j = 0; j < 4; j++) {
            if (v[j] <= thresh) {
                int code = base + j;
                const float* cr = cb + (size_t)code * DDIM;
                float dot = 0.f;
                #pragma unroll 8
                for (int d = 0; d < DDIM; d++) dot = fmaf(zr[d], cr[d], dot);
                float ed = fmaf(-2.f, dot, g_c_sq[code]);
                if (ed < ebest || (ed == ebest && code < eidx)) { ebest = ed; eidx = code; }
            }
        }
    }
    #pragma unroll
    for (int o = 16; o; o >>= 1) {
        float ob = __shfl_xor_sync(0xffffffffu, ebest, o);
        int   oi = __shfl_xor_sync(0xffffffffu, eidx, o);
        if (ob < ebest || (ob == ebest && oi < eidx)) { ebest = ob; eidx = oi; }
    }

    if (lane == 0) idx_out[m] = (float)eidx;
    const float4* crow = (const float4*)(cb + (size_t)eidx * DDIM);
    float4* zrow = (float4*)(zq + (size_t)m * DDIM);
    zrow[lane]      = crow[lane];
    zrow[lane + 32] = crow[lane + 32];
}

extern "C" void kernel_launch(void* const* d_in, const int* in_sizes, int n_in,
                              void* d_out, int out_size) {
    const float* z  = (const float*)d_in[0];
    const float* cb = (const float*)d_in[1];
    float* out    = (float*)d_out;
    float* zq     = out;                        // [MTOT, DDIM]
    float* idxout = out + (size_t)MTOT * DDIM;  // [MTOT] as float

    csq_kernel<<<(KCODES * 32 + 255) / 256, 256>>>(cb);
    z_tobf16_kernel<<<(MTOT * DDIM / 4 + 255) / 256, 256>>>(z);
    cb_tobf16_kernel<<<(KCODES * DDIM / 4 + 255) / 256, 256>>>(cb);
    vq_phase1<<<MTOT / BM, 256>>>();
    vq_phase2<<<MTOT / 8, 256>>>(z, cb, zq, idxout);
}